// round 13
// baseline (speedup 1.0000x reference)
#include <cuda_runtime.h>
#include <cuda_fp16.h>
#include <math.h>

#define NN 50000
#define EE 500000
#define DD 128
#define HH 8
#define LL 2
#define FFD 512
#define NE (EE + NN)
#define BM 128

// ---------------- scratch ----------------------------------------------------
__device__ __align__(16) __half g_xn[NN * DD];
__device__ __align__(16) __half g_qkv[NN * 3 * DD];
__device__ __align__(16) __half g_aggr[NN * DD];
__device__ __align__(16) __half g_h[NN * FFD];
__device__ float  g_deg[NN];
__device__ float  g_degn[NN];
__device__ double g_stats[2];
__device__ __align__(16) __half g_weff[3 * DD * DD];   // transposed [384][128]
__device__ float  g_beff[3 * DD];
__device__ float  g_wdegeff[3 * DD];
__device__ __align__(16) __half g_wo[LL * DD * DD];    // transposed, both layers
__device__ __align__(16) __half g_w1[LL * FFD * DD];
__device__ __align__(16) __half g_w2[LL * DD * FFD];
__device__ int    g_ddeg[NN];
__device__ int    g_off[NN + 1];
__device__ int    g_cur[NN];
__device__ int    g_csr[NE];

__device__ __forceinline__ unsigned h2u(__half2 h) {
    unsigned u;
    memcpy(&u, &h, 4);
    return u;
}

// ---------------- prep --------------------------------------------------------
__global__ void k_prep(float* deg, int* ddeg, double* st) {
    int i = blockIdx.x * blockDim.x + threadIdx.x;
    if (i < NN) { deg[i] = 1.f; ddeg[i] = 1; }
    if (i == 0) { st[0] = 0.0; st[1] = 0.0; }
}

// ---------------- degree + CSR build -------------------------------------------
__global__ void k_degcount2(const int* __restrict__ ei, float* deg, int* ddeg) {
    int e = blockIdx.x * blockDim.x + threadIdx.x;
    if (e < EE) {
        atomicAdd(&deg[ei[e]], 1.0f);
        atomicAdd(&ddeg[ei[EE + e]], 1);
    }
}
// exclusive scan over ddeg + self-loop seeding of csr/cur (fused)
__global__ void k_scan(const int* __restrict__ ddeg, int* __restrict__ off,
                       int* __restrict__ cur, int* __restrict__ csr) {
    __shared__ int wsum[32];
    __shared__ int carry;
    int t = threadIdx.x, lane = t & 31, wid = t >> 5;
    if (t == 0) { carry = 0; off[0] = 0; }
    __syncthreads();
    for (int base = 0; base < NN; base += 1024) {
        int i = base + t;
        int v = (i < NN) ? ddeg[i] : 0;
        int s = v;
        #pragma unroll
        for (int o = 1; o < 32; o <<= 1) {
            int u = __shfl_up_sync(0xffffffffu, s, o);
            if (lane >= o) s += u;
        }
        if (lane == 31) wsum[wid] = s;
        __syncthreads();
        if (wid == 0) {
            int ws = wsum[lane];
            #pragma unroll
            for (int o = 1; o < 32; o <<= 1) {
                int u = __shfl_up_sync(0xffffffffu, ws, o);
                if (lane >= o) ws += u;
            }
            wsum[lane] = ws;
        }
        __syncthreads();
        int add = (wid > 0) ? wsum[wid - 1] : 0;
        int incl = s + add + carry;
        if (i < NN) {
            off[i + 1] = incl;
            int oi = incl - v;
            csr[oi] = i;          // self loop first
            cur[i] = oi + 1;
        }
        __syncthreads();
        if (t == 1023) carry = incl;
        __syncthreads();
    }
}
__global__ void k_csr_scatter(const int* __restrict__ ei, int* cur, int* csr) {
    int e = blockIdx.x * blockDim.x + threadIdx.x;
    if (e >= EE) return;
    int dst = ei[EE + e];
    int pos = atomicAdd(&cur[dst], 1);
    csr[pos] = ei[e];
}

__global__ void k_deg_reduce(const float* __restrict__ deg, double* st) {
    __shared__ double ss[256], sq[256];
    int t = threadIdx.x;
    double s = 0.0, q = 0.0;
    for (int i = blockIdx.x * blockDim.x + t; i < NN; i += gridDim.x * blockDim.x) {
        double d = (double)deg[i];
        s += d; q += d * d;
    }
    ss[t] = s; sq[t] = q;
    __syncthreads();
    for (int o = 128; o > 0; o >>= 1) {
        if (t < o) { ss[t] += ss[t + o]; sq[t] += sq[t + o]; }
        __syncthreads();
    }
    if (t == 0) { atomicAdd(&st[0], ss[0]); atomicAdd(&st[1], sq[0]); }
}
__global__ void k_deg_norm(const float* __restrict__ deg, const double* __restrict__ st,
                           float* __restrict__ degn) {
    int i = blockIdx.x * blockDim.x + threadIdx.x;
    if (i >= NN) return;
    double mean = st[0] / (double)NN;
    double var  = (st[1] - st[0] * st[0] / (double)NN) / (double)(NN - 1);
    float  sd   = (float)sqrt(var);
    degn[i] = (deg[i] - (float)mean) / (sd + 1e-6f);
}

// ---------------- folded effective weights (fp16, TRANSPOSED [N][K]) -----------
__global__ void k_weff(const float* __restrict__ Wq, const float* __restrict__ Wk,
                       const float* __restrict__ Wv, const float* __restrict__ Wpos,
                       const float* __restrict__ Wdeg,
                       const float* __restrict__ bq, const float* __restrict__ bk,
                       const float* __restrict__ bv, const float* __restrict__ bpos,
                       const float* __restrict__ bdeg,
                       __half* __restrict__ weff, float* __restrict__ beff,
                       float* __restrict__ wdegeff) {
    int j = blockIdx.x;
    int t = threadIdx.x;
    const float* W  = (j < DD) ? Wq : ((j < 2 * DD) ? Wk : Wv);
    const float* bb = (j < DD) ? bq : ((j < 2 * DD) ? bk : bv);
    int jj = j & (DD - 1);
    __shared__ float col[DD];
    col[t] = W[t * DD + jj];
    __syncthreads();
    float acc = col[t];
    #pragma unroll 8
    for (int m = 0; m < DD; m++) acc += Wpos[t * DD + m] * col[m];
    weff[j * DD + t] = __float2half_rn(acc);
    if (t == 0) {
        float s = 0.f;
        for (int m = 0; m < DD; m++) s += (bpos[m] + bdeg[m]) * col[m];
        beff[j] = s + bb[jj];
    }
    if (t == 1) {
        float s = 0.f;
        for (int m = 0; m < DD; m++) s += Wdeg[m] * col[m];
        wdegeff[j] = s;
    }
}

// convert + transpose BOTH layers' weights to fp16 [N][K]
__global__ void k_cvtw(const float* __restrict__ Wo, const float* __restrict__ W1,
                       const float* __restrict__ W2, __half* wo, __half* w1, __half* w2) {
    int i = blockIdx.x * blockDim.x + threadIdx.x;
    int l = blockIdx.y;
    const float* Wo_l = Wo + (size_t)l * DD * DD;
    const float* W1_l = W1 + (size_t)l * DD * FFD;
    const float* W2_l = W2 + (size_t)l * FFD * DD;
    __half* wo_l = wo + (size_t)l * DD * DD;
    __half* w1_l = w1 + (size_t)l * FFD * DD;
    __half* w2_l = w2 + (size_t)l * DD * FFD;
    if (i < DD * DD) {
        int k = i / DD, n = i % DD;
        wo_l[n * DD + k] = __float2half_rn(Wo_l[i]);
    }
    if (i < DD * FFD) {
        int k1 = i / FFD, n1 = i % FFD;
        w1_l[n1 * DD + k1] = __float2half_rn(W1_l[i]);
        int k2 = i / DD, n2 = i % DD;
        w2_l[n2 * FFD + k2] = __float2half_rn(W2_l[i]);
    }
}

// ---------------- LayerNorm (warp per node, fp16 output) -----------------------
__global__ void k_layernorm(const float* __restrict__ x, const float* __restrict__ g,
                            const float* __restrict__ b, __half* __restrict__ out) {
    int node = (blockIdx.x * blockDim.x + threadIdx.x) >> 5;
    int lane = threadIdx.x & 31;
    if (node >= NN) return;
    const float4 v = *(const float4*)(x + (long)node * DD + lane * 4);
    float s = v.x + v.y + v.z + v.w;
    #pragma unroll
    for (int o = 16; o > 0; o >>= 1) s += __shfl_xor_sync(0xffffffffu, s, o);
    float mu = s * (1.0f / DD);
    float dx = v.x - mu, dy = v.y - mu, dz = v.z - mu, dw = v.w - mu;
    float q = dx * dx + dy * dy + dz * dz + dw * dw;
    #pragma unroll
    for (int o = 16; o > 0; o >>= 1) q += __shfl_xor_sync(0xffffffffu, q, o);
    float rs = rsqrtf(q * (1.0f / DD) + 1e-5f);
    const float4 gg = *(const float4*)(g + lane * 4);
    const float4 bb = *(const float4*)(b + lane * 4);
    __half2 h0 = __floats2half2_rn(dx * rs * gg.x + bb.x, dy * rs * gg.y + bb.y);
    __half2 h1 = __floats2half2_rn(dz * rs * gg.z + bb.z, dw * rs * gg.w + bb.w);
    uint2 u = make_uint2(h2u(h0), h2u(h1));
    *(uint2*)(out + (long)node * DD + lane * 4) = u;
}

// ---------------- 3-stage pipelined fp16 GEMM (m16n8k16, fp32 accum) -----------
// C[M,N] = A[M,K] @ Bt[N,K]^T (+epilogue). BN = NT*16, K-chunk 64 halves.
// mode 0: half out  = acc + bias + degn[i]*wdeg[j]
// mode 1: float out = acc + bias + C
// mode 2: half out  = gelu(acc + bias)
// mode 3: float C += acc + bias;  half xnout = LayerNorm(rows of C)  [NT==8, N==128]
#define BKH 64
#define LDH 72
#define NSTAGE 3
#define ASTAGE_H (BM * LDH)

__device__ __forceinline__ unsigned smemu32(const void* p) {
    return (unsigned)__cvta_generic_to_shared(p);
}

template<int NT>
__global__ __launch_bounds__(256, 2) void gemm_hf(
    const __half* __restrict__ A, const __half* __restrict__ Bt, void* Cv,
    const float* __restrict__ bias, const float* __restrict__ wdegv,
    const float* __restrict__ degn, const float* __restrict__ lng,
    const float* __restrict__ lnb, __half* __restrict__ xnout,
    int M, int N, int K, int mode) {
    constexpr int BN = NT * 16;
    constexpr int BSTAGE_H = BN * LDH;
    extern __shared__ __half sm[];
    __half* As = sm;                           // [NSTAGE][BM][LDH]
    __half* Bs = sm + NSTAGE * ASTAGE_H;       // [NSTAGE][BN][LDH]

    const int tid  = threadIdx.x;
    const int warp = tid >> 5;
    const int lane = tid & 31;
    const int wm = warp >> 1;
    const int wn = warp & 1;
    const int g  = lane >> 2;
    const int q  = lane & 3;
    const int rowBase = blockIdx.y * BM;
    const int colBase = blockIdx.x * BN;

    float acc[2][NT][4];
    #pragma unroll
    for (int i = 0; i < 2; i++)
        #pragma unroll
        for (int j = 0; j < NT; j++)
            #pragma unroll
            for (int k = 0; k < 4; k++) acc[i][j][k] = 0.0f;

    const int nk = K / BKH;

    auto loadA = [&](int s, int k0) {
        #pragma unroll
        for (int i = 0; i < 4; i++) {
            int idx = tid + i * 256;
            int r = idx >> 3, c = (idx & 7) * 8;
            int grow = rowBase + r;
            const __half* src = A + (long)(grow < M ? grow : M - 1) * K + k0 + c;
            int sz = (grow < M) ? 16 : 0;
            asm volatile("cp.async.cg.shared.global [%0], [%1], 16, %2;"
                         :: "r"(smemu32(As + s * ASTAGE_H + r * LDH + c)), "l"(src), "r"(sz));
        }
    };
    auto loadB = [&](int s, int k0) {
        #pragma unroll
        for (int i = 0; i < NT / 2; i++) {
            int idx = tid + i * 256;
            int n = idx >> 3, c = (idx & 7) * 8;
            const __half* src = Bt + (long)(colBase + n) * K + k0 + c;
            asm volatile("cp.async.cg.shared.global [%0], [%1], 16;"
                         :: "r"(smemu32(Bs + s * BSTAGE_H + n * LDH + c)), "l"(src));
        }
    };

    unsigned aBase = smemu32(As);
    unsigned bBase = smemu32(Bs);
    unsigned offA[2], offB[NT / 2];
    #pragma unroll
    for (int mt = 0; mt < 2; mt++) {
        int row = wm * 32 + mt * 16 + (lane & 15);
        int kh  = (lane >> 4) << 3;
        offA[mt] = (unsigned)((row * LDH + kh) * 2);
    }
    #pragma unroll
    for (int p = 0; p < NT / 2; p++) {
        int row = wn * (NT * 8) + p * 16 + ((lane >> 4) << 3) + (lane & 7);
        int kh  = ((lane >> 3) & 1) << 3;
        offB[p] = (unsigned)((row * LDH + kh) * 2);
    }

    loadA(0, 0); loadB(0, 0);
    asm volatile("cp.async.commit_group;");
    if (nk > 1) { loadA(1, BKH); loadB(1, BKH); }
    asm volatile("cp.async.commit_group;");

    int buf = 0;
    for (int kb = 0; kb < nk; kb++) {
        asm volatile("cp.async.wait_group 1;");
        __syncthreads();
        if (kb + 2 < nk) {
            int s = (kb + 2) % NSTAGE;
            loadA(s, (kb + 2) * BKH);
            loadB(s, (kb + 2) * BKH);
        }
        asm volatile("cp.async.commit_group;");

        unsigned aStage = aBase + buf * (ASTAGE_H * 2);
        unsigned bStage = bBase + buf * (BSTAGE_H * 2);
        #pragma unroll
        for (int kk = 0; kk < BKH; kk += 16) {
            unsigned a_frag[2][4];
            #pragma unroll
            for (int mt = 0; mt < 2; mt++) {
                asm volatile("ldmatrix.sync.aligned.m8n8.x4.shared.b16 "
                             "{%0,%1,%2,%3}, [%4];"
                             : "=r"(a_frag[mt][0]), "=r"(a_frag[mt][1]),
                               "=r"(a_frag[mt][2]), "=r"(a_frag[mt][3])
                             : "r"(aStage + offA[mt] + kk * 2));
            }
            unsigned b_frag[NT][2];
            #pragma unroll
            for (int p = 0; p < NT / 2; p++) {
                asm volatile("ldmatrix.sync.aligned.m8n8.x4.shared.b16 "
                             "{%0,%1,%2,%3}, [%4];"
                             : "=r"(b_frag[2 * p][0]), "=r"(b_frag[2 * p][1]),
                               "=r"(b_frag[2 * p + 1][0]), "=r"(b_frag[2 * p + 1][1])
                             : "r"(bStage + offB[p] + kk * 2));
            }
            #pragma unroll
            for (int mt = 0; mt < 2; mt++)
                #pragma unroll
                for (int nt = 0; nt < NT; nt++) {
                    asm volatile(
                        "mma.sync.aligned.m16n8k16.row.col.f32.f16.f16.f32 "
                        "{%0,%1,%2,%3}, {%4,%5,%6,%7}, {%8,%9}, {%0,%1,%2,%3};"
                        : "+f"(acc[mt][nt][0]), "+f"(acc[mt][nt][1]),
                          "+f"(acc[mt][nt][2]), "+f"(acc[mt][nt][3])
                        : "r"(a_frag[mt][0]), "r"(a_frag[mt][1]),
                          "r"(a_frag[mt][2]), "r"(a_frag[mt][3]),
                          "r"(b_frag[nt][0]), "r"(b_frag[nt][1]));
                }
        }
        __syncthreads();
        buf = (buf + 1 == NSTAGE) ? 0 : buf + 1;
    }

    if (mode == 3) {
        // residual + fused LayerNorm (requires NT==8, N==128, grid.x==1)
        if constexpr (NT == 8) {
            float* red = (float*)sm;    // stage buffers dead; 1024 floats reused
            #pragma unroll
            for (int mt = 0; mt < 2; mt++) {
                #pragma unroll
                for (int half = 0; half < 2; half++) {
                    int gr = rowBase + wm * 32 + mt * 16 + g + half * 8;
                    float ls = 0.f, lq = 0.f;
                    if (gr < M) {
                        #pragma unroll
                        for (int nt = 0; nt < NT; nt++) {
                            int gc = wn * 64 + nt * 8 + q * 2;
                            float* cp = (float*)Cv + (long)gr * N + gc;
                            float2 old = *(const float2*)cp;
                            float v0 = acc[mt][nt][half * 2 + 0] + bias[gc] + old.x;
                            float v1 = acc[mt][nt][half * 2 + 1] + bias[gc + 1] + old.y;
                            *(float2*)cp = make_float2(v0, v1);
                            acc[mt][nt][half * 2 + 0] = v0;
                            acc[mt][nt][half * 2 + 1] = v1;
                            ls += v0 + v1;
                            lq += v0 * v0 + v1 * v1;
                        }
                    }
                    ls += __shfl_xor_sync(0xffffffffu, ls, 1);
                    ls += __shfl_xor_sync(0xffffffffu, ls, 2);
                    lq += __shfl_xor_sync(0xffffffffu, lq, 1);
                    lq += __shfl_xor_sync(0xffffffffu, lq, 2);
                    if (q == 0 && gr < M) {
                        int idx = (((wm * 2 + mt) * 2 + half) * 8 + g) * 2 + wn;
                        red[idx] = ls;
                        red[512 + idx] = lq;
                    }
                }
            }
            __syncthreads();
            #pragma unroll
            for (int mt = 0; mt < 2; mt++) {
                #pragma unroll
                for (int half = 0; half < 2; half++) {
                    int gr = rowBase + wm * 32 + mt * 16 + g + half * 8;
                    if (gr >= M) continue;
                    int i0 = (((wm * 2 + mt) * 2 + half) * 8 + g) * 2;
                    float ts = red[i0] + red[i0 + 1];
                    float tq = red[512 + i0] + red[512 + i0 + 1];
                    float mu = ts * (1.0f / 128.0f);
                    float var = tq * (1.0f / 128.0f) - mu * mu;
                    float rsg = rsqrtf(var + 1e-5f);
                    #pragma unroll
                    for (int nt = 0; nt < NT; nt++) {
                        int gc = wn * 64 + nt * 8 + q * 2;
                        float v0 = (acc[mt][nt][half * 2 + 0] - mu) * rsg * lng[gc] + lnb[gc];
                        float v1 = (acc[mt][nt][half * 2 + 1] - mu) * rsg * lng[gc + 1] + lnb[gc + 1];
                        __half* xp = xnout + (long)gr * N + gc;
                        *(__half2*)xp = __floats2half2_rn(v0, v1);
                    }
                }
            }
        }
        return;
    }

    #pragma unroll
    for (int mt = 0; mt < 2; mt++) {
        #pragma unroll
        for (int half = 0; half < 2; half++) {
            int gr = rowBase + wm * 32 + mt * 16 + g + half * 8;
            if (gr >= M) continue;
            float dn = (mode == 0) ? degn[gr] : 0.0f;
            #pragma unroll
            for (int nt = 0; nt < NT; nt++) {
                int gc = colBase + wn * (NT * 8) + nt * 8 + q * 2;
                float v0 = acc[mt][nt][half * 2 + 0] + bias[gc];
                float v1 = acc[mt][nt][half * 2 + 1] + bias[gc + 1];
                if (mode == 1) {
                    float* cp = (float*)Cv + (long)gr * N + gc;
                    float2 old = *(const float2*)cp;
                    *(float2*)cp = make_float2(v0 + old.x, v1 + old.y);
                } else {
                    if (mode == 0) {
                        v0 += dn * wdegv[gc];
                        v1 += dn * wdegv[gc + 1];
                    } else {
                        v0 = 0.5f * v0 * (1.0f + erff(v0 * 0.70710678118654752f));
                        v1 = 0.5f * v1 * (1.0f + erff(v1 * 0.70710678118654752f));
                    }
                    __half* cp = (__half*)Cv + (long)gr * N + gc;
                    *(__half2*)cp = __floats2half2_rn(v0, v1);
                }
            }
        }
    }
}
#define SMEM8 (NSTAGE * (ASTAGE_H + 128 * LDH) * (int)sizeof(__half))
#define SMEM4 (NSTAGE * (ASTAGE_H + 64 * LDH) * (int)sizeof(__half))

// ---------------- fused CSR attention, software-pipelined (warp per dst) -------
__device__ __forceinline__ float4 u2f4(uint2 u) {
    __half2 h0, h1;
    memcpy(&h0, &u.x, 4);
    memcpy(&h1, &u.y, 4);
    float2 a = __half22float2(h0);
    float2 b = __half22float2(h1);
    return make_float4(a.x, a.y, b.x, b.y);
}
__device__ __forceinline__ float4 ld4h(const __half* p) {
    return u2f4(*(const uint2*)p);
}

__global__ __launch_bounds__(256) void k_attn(
    const int* __restrict__ off, const int* __restrict__ csr,
    const __half* __restrict__ qkv, __half* __restrict__ aggr) {
    int w = (blockIdx.x * blockDim.x + threadIdx.x) >> 5;
    int lane = threadIdx.x & 31;
    if (w >= NN) return;
    const int beg = off[w], end = off[w + 1];

    float4 qv = ld4h(qkv + (long)w * 384 + lane * 4);

    float s_acc = 0.0f;
    float ax = 0.f, ay = 0.f, az = 0.f, aw = 0.f;

    // prefetch stage (2 edges, raw halves)
    int e = beg;
    int sa0 = csr[e];
    int sa1 = csr[(e + 1 < end) ? e + 1 : e];
    uint2 ka0 = *(const uint2*)(qkv + (long)sa0 * 384 + 128 + lane * 4);
    uint2 ka1 = *(const uint2*)(qkv + (long)sa1 * 384 + 128 + lane * 4);
    uint2 va0 = *(const uint2*)(qkv + (long)sa0 * 384 + 256 + lane * 4);
    uint2 va1 = *(const uint2*)(qkv + (long)sa1 * 384 + 256 + lane * 4);

    for (; e < end; e += 2) {
        // issue next stage's loads before computing on current stage
        uint2 kb0, kb1, vb0, vb1;
        int ne = e + 2;
        if (ne < end) {
            int sb0 = csr[ne];
            int sb1 = csr[(ne + 1 < end) ? ne + 1 : ne];
            kb0 = *(const uint2*)(qkv + (long)sb0 * 384 + 128 + lane * 4);
            kb1 = *(const uint2*)(qkv + (long)sb1 * 384 + 128 + lane * 4);
            vb0 = *(const uint2*)(qkv + (long)sb0 * 384 + 256 + lane * 4);
            vb1 = *(const uint2*)(qkv + (long)sb1 * 384 + 256 + lane * 4);
        }
        // compute on buffered stage
        float4 k0 = u2f4(ka0), k1 = u2f4(ka1);
        float4 v0 = u2f4(va0), v1 = u2f4(va1);
        float p0 = qv.x * k0.x + qv.y * k0.y + qv.z * k0.z + qv.w * k0.w;
        float p1 = qv.x * k1.x + qv.y * k1.y + qv.z * k1.z + qv.w * k1.w;
        p0 += __shfl_xor_sync(0xffffffffu, p0, 1);
        p0 += __shfl_xor_sync(0xffffffffu, p0, 2);
        p1 += __shfl_xor_sync(0xffffffffu, p1, 1);
        p1 += __shfl_xor_sync(0xffffffffu, p1, 2);
        float ex0 = __expf(fminf(fmaxf(p0 * 0.25f, -50.f), 50.f));
        float ex1 = __expf(fminf(fmaxf(p1 * 0.25f, -50.f), 50.f));
        if (e + 1 >= end) ex1 = 0.0f;          // masked padding edge
        s_acc += ex0 + ex1;
        ax += ex0 * v0.x + ex1 * v1.x;
        ay += ex0 * v0.y + ex1 * v1.y;
        az += ex0 * v0.z + ex1 * v1.z;
        aw += ex0 * v0.w + ex1 * v1.w;
        // rotate buffers
        ka0 = kb0; ka1 = kb1; va0 = vb0; va1 = vb1;
    }

    float rs = 1.0f / (s_acc + 1e-16f);
    __half2 h0 = __floats2half2_rn(ax * rs, ay * rs);
    __half2 h1 = __floats2half2_rn(az * rs, aw * rs);
    uint2 u = make_uint2(h2u(h0), h2u(h1));
    *(uint2*)(aggr + (long)w * DD + lane * 4) = u;
}

// ---------------- driver --------------------------------------------------------
extern "C" void kernel_launch(void* const* d_in, const int* in_sizes, int n_in,
                              void* d_out, int out_size) {
    const float* x    = (const float*)d_in[0];
    const int*   ei   = (const int*)d_in[1];
    const float* Wq   = (const float*)d_in[2];
    const float* Wk   = (const float*)d_in[3];
    const float* Wv   = (const float*)d_in[4];
    const float* Wo   = (const float*)d_in[5];
    const float* Wpos = (const float*)d_in[6];
    const float* Wdeg = (const float*)d_in[7];
    const float* W1   = (const float*)d_in[8];
    const float* W2   = (const float*)d_in[9];
    const float* bq   = (const float*)d_in[10];
    const float* bk   = (const float*)d_in[11];
    const float* bv   = (const float*)d_in[12];
    const float* bo   = (const float*)d_in[13];
    const float* bpos = (const float*)d_in[14];
    const float* bdeg = (const float*)d_in[15];
    const float* ln1b = (const float*)d_in[16];
    const float* ln2b = (const float*)d_in[17];
    const float* b1   = (const float*)d_in[18];
    const float* b2   = (const float*)d_in[19];
    const float* ln1g = (const float*)d_in[20];
    const float* ln2g = (const float*)d_in[21];
    float* xbuf = (float*)d_out;

    __half *xn, *qkv, *aggr, *hb, *weff, *wo, *w1, *w2;
    float *deg, *degn, *beff, *wde;
    int *ddeg, *off, *cur, *csr;
    double* stats;
    cudaGetSymbolAddress((void**)&xn,    g_xn);
    cudaGetSymbolAddress((void**)&qkv,   g_qkv);
    cudaGetSymbolAddress((void**)&aggr,  g_aggr);
    cudaGetSymbolAddress((void**)&hb,    g_h);
    cudaGetSymbolAddress((void**)&deg,   g_deg);
    cudaGetSymbolAddress((void**)&degn,  g_degn);
    cudaGetSymbolAddress((void**)&weff,  g_weff);
    cudaGetSymbolAddress((void**)&beff,  g_beff);
    cudaGetSymbolAddress((void**)&wde,   g_wdegeff);
    cudaGetSymbolAddress((void**)&wo,    g_wo);
    cudaGetSymbolAddress((void**)&w1,    g_w1);
    cudaGetSymbolAddress((void**)&w2,    g_w2);
    cudaGetSymbolAddress((void**)&ddeg,  g_ddeg);
    cudaGetSymbolAddress((void**)&off,   g_off);
    cudaGetSymbolAddress((void**)&cur,   g_cur);
    cudaGetSymbolAddress((void**)&csr,   g_csr);
    cudaGetSymbolAddress((void**)&stats, g_stats);

    cudaFuncSetAttribute((void*)gemm_hf<8>,
                         cudaFuncAttributeMaxDynamicSharedMemorySize, SMEM8);
    cudaFuncSetAttribute((void*)gemm_hf<4>,
                         cudaFuncAttributeMaxDynamicSharedMemorySize, SMEM4);

    cudaMemcpyAsync(xbuf, x, (size_t)NN * DD * sizeof(float), cudaMemcpyDeviceToDevice);

    const int rowBlocks = (NN + BM - 1) / BM;
    const int lnBlocks  = (NN + 7) / 8;
    const int nodeWarpBlocks = (NN + 7) / 8;

    k_weff<<<3 * DD, DD>>>(Wq, Wk, Wv, Wpos, Wdeg, bq, bk, bv, bpos, bdeg,
                           weff, beff, wde);
    k_layernorm<<<lnBlocks, 256>>>(xbuf, ln1g, ln1b, xn);
    k_prep<<<(NN + 255) / 256, 256>>>(deg, ddeg, stats);
    k_degcount2<<<(EE + 255) / 256, 256>>>(ei, deg, ddeg);
    k_deg_reduce<<<148, 256>>>(deg, stats);
    k_deg_norm<<<(NN + 255) / 256, 256>>>(deg, stats, degn);
    gemm_hf<8><<<dim3(3, rowBlocks), 256, SMEM8>>>(
        xn, weff, qkv, beff, wde, degn, nullptr, nullptr, nullptr,
        NN, 3 * DD, DD, 0);

    k_scan<<<1, 1024>>>(ddeg, off, cur, csr);
    k_csr_scatter<<<(EE + 255) / 256, 256>>>(ei, cur, csr);
    k_cvtw<<<dim3((DD * FFD + 255) / 256, LL), 256>>>(Wo, W1, W2, wo, w1, w2);

    for (int l = 0; l < LL; l++) {
        __half* wo_l = wo + (size_t)l * DD * DD;
        __half* w1_l = w1 + (size_t)l * FFD * DD;
        __half* w2_l = w2 + (size_t)l * DD * FFD;
        k_attn<<<nodeWarpBlocks, 256>>>(off, csr, qkv, aggr);
        // Wo GEMM with fused residual + LN2 -> xn
        gemm_hf<8><<<dim3(1, rowBlocks), 256, SMEM8>>>(
            aggr, wo_l, xbuf, bo + l * DD, nullptr, nullptr,
            ln2g + l * DD, ln2b + l * DD, xn, NN, DD, DD, 3);
        gemm_hf<8><<<dim3(4, rowBlocks), 256, SMEM8>>>(
            xn, w1_l, hb, b1 + l * FFD, nullptr, nullptr, nullptr, nullptr, nullptr,
            NN, FFD, DD, 2);
        if (l + 1 < LL) {
            int n = l + 1;
            // W2 GEMM with fused residual + next layer's LN1 -> xn
            gemm_hf<8><<<dim3(1, rowBlocks), 256, SMEM8>>>(
                hb, w2_l, xbuf, b2 + l * DD, nullptr, nullptr,
                ln1g + n * DD, ln1b + n * DD, xn, NN, DD, FFD, 3);
            k_weff<<<3 * DD, DD>>>(Wq + (size_t)n * DD * DD, Wk + (size_t)n * DD * DD,
                                   Wv + (size_t)n * DD * DD, Wpos + (size_t)n * DD * DD,
                                   Wdeg + (size_t)n * DD,
                                   bq + n * DD, bk + n * DD, bv + n * DD,
                                   bpos + n * DD, bdeg + n * DD, weff, beff, wde);
            gemm_hf<8><<<dim3(3, rowBlocks), 256, SMEM8>>>(
                xn, weff, qkv, beff, wde, degn, nullptr, nullptr, nullptr,
                NN, 3 * DD, DD, 0);
        } else {
            // final W2 GEMM: plain residual
            gemm_hf<4><<<dim3(2, rowBlocks), 256, SMEM4>>>(
                hb, w2_l, xbuf, b2 + l * DD, nullptr, nullptr, nullptr, nullptr, nullptr,
                NN, DD, FFD, 1);
        }
    }
}

// round 14
// speedup vs baseline: 1.1104x; 1.1104x over previous
#include <cuda_runtime.h>
#include <cuda_fp16.h>
#include <math.h>

#define NN 50000
#define EE 500000
#define DD 128
#define HH 8
#define LL 2
#define FFD 512
#define NE (EE + NN)
#define BM 128

// ---------------- scratch ----------------------------------------------------
__device__ __align__(16) __half g_xn[NN * DD];
__device__ __align__(16) __half g_qkv[NN * 3 * DD];
__device__ __align__(16) __half g_aggr[NN * DD];
__device__ __align__(16) __half g_h[NN * FFD];
__device__ float  g_deg[NN];
__device__ float  g_degn[NN];
__device__ double g_stats[2];
__device__ __align__(16) __half g_weff[LL * 3 * DD * DD];  // transposed, both layers
__device__ float  g_beff[LL * 3 * DD];
__device__ float  g_wdegeff[LL * 3 * DD];
__device__ __align__(16) __half g_wo[LL * DD * DD];
__device__ __align__(16) __half g_w1[LL * FFD * DD];
__device__ __align__(16) __half g_w2[LL * DD * FFD];
__device__ int    g_ddeg[NN];
__device__ int    g_off[NN + 1];
__device__ int    g_cur[NN];
__device__ int    g_csr[NE];

__device__ __forceinline__ unsigned h2u(__half2 h) {
    unsigned u;
    memcpy(&u, &h, 4);
    return u;
}

// ---------------- prep --------------------------------------------------------
__global__ void k_prep(float* deg, int* ddeg, double* st) {
    int i = blockIdx.x * blockDim.x + threadIdx.x;
    if (i < NN) { deg[i] = 1.f; ddeg[i] = 1; }
    if (i == 0) { st[0] = 0.0; st[1] = 0.0; }
}

// ---------------- degree + CSR build -------------------------------------------
__global__ void k_degcount2(const int* __restrict__ ei, float* deg, int* ddeg) {
    int e = blockIdx.x * blockDim.x + threadIdx.x;
    if (e < EE) {
        atomicAdd(&deg[ei[e]], 1.0f);
        atomicAdd(&ddeg[ei[EE + e]], 1);
    }
}
__global__ void k_scan(const int* __restrict__ ddeg, int* __restrict__ off,
                       int* __restrict__ cur, int* __restrict__ csr) {
    __shared__ int wsum[32];
    __shared__ int carry;
    int t = threadIdx.x, lane = t & 31, wid = t >> 5;
    if (t == 0) { carry = 0; off[0] = 0; }
    __syncthreads();
    for (int base = 0; base < NN; base += 1024) {
        int i = base + t;
        int v = (i < NN) ? ddeg[i] : 0;
        int s = v;
        #pragma unroll
        for (int o = 1; o < 32; o <<= 1) {
            int u = __shfl_up_sync(0xffffffffu, s, o);
            if (lane >= o) s += u;
        }
        if (lane == 31) wsum[wid] = s;
        __syncthreads();
        if (wid == 0) {
            int ws = wsum[lane];
            #pragma unroll
            for (int o = 1; o < 32; o <<= 1) {
                int u = __shfl_up_sync(0xffffffffu, ws, o);
                if (lane >= o) ws += u;
            }
            wsum[lane] = ws;
        }
        __syncthreads();
        int add = (wid > 0) ? wsum[wid - 1] : 0;
        int incl = s + add + carry;
        if (i < NN) {
            off[i + 1] = incl;
            int oi = incl - v;
            csr[oi] = i;
            cur[i] = oi + 1;
        }
        __syncthreads();
        if (t == 1023) carry = incl;
        __syncthreads();
    }
}
__global__ void k_csr_scatter(const int* __restrict__ ei, int* cur, int* csr) {
    int e = blockIdx.x * blockDim.x + threadIdx.x;
    if (e >= EE) return;
    int dst = ei[EE + e];
    int pos = atomicAdd(&cur[dst], 1);
    csr[pos] = ei[e];
}

__global__ void k_deg_reduce(const float* __restrict__ deg, double* st) {
    __shared__ double ss[256], sq[256];
    int t = threadIdx.x;
    double s = 0.0, q = 0.0;
    for (int i = blockIdx.x * blockDim.x + t; i < NN; i += gridDim.x * blockDim.x) {
        double d = (double)deg[i];
        s += d; q += d * d;
    }
    ss[t] = s; sq[t] = q;
    __syncthreads();
    for (int o = 128; o > 0; o >>= 1) {
        if (t < o) { ss[t] += ss[t + o]; sq[t] += sq[t + o]; }
        __syncthreads();
    }
    if (t == 0) { atomicAdd(&st[0], ss[0]); atomicAdd(&st[1], sq[0]); }
}
__global__ void k_deg_norm(const float* __restrict__ deg, const double* __restrict__ st,
                           float* __restrict__ degn) {
    int i = blockIdx.x * blockDim.x + threadIdx.x;
    if (i >= NN) return;
    double mean = st[0] / (double)NN;
    double var  = (st[1] - st[0] * st[0] / (double)NN) / (double)(NN - 1);
    float  sd   = (float)sqrt(var);
    degn[i] = (deg[i] - (float)mean) / (sd + 1e-6f);
}

// ---------------- folded effective weights (fp16, TRANSPOSED [N][K]) -----------
__global__ void k_weff(const float* __restrict__ Wq, const float* __restrict__ Wk,
                       const float* __restrict__ Wv, const float* __restrict__ Wpos,
                       const float* __restrict__ Wdeg,
                       const float* __restrict__ bq, const float* __restrict__ bk,
                       const float* __restrict__ bv, const float* __restrict__ bpos,
                       const float* __restrict__ bdeg,
                       __half* __restrict__ weff, float* __restrict__ beff,
                       float* __restrict__ wdegeff) {
    int j = blockIdx.x;
    int t = threadIdx.x;
    const float* W  = (j < DD) ? Wq : ((j < 2 * DD) ? Wk : Wv);
    const float* bb = (j < DD) ? bq : ((j < 2 * DD) ? bk : bv);
    int jj = j & (DD - 1);
    __shared__ float col[DD];
    col[t] = W[t * DD + jj];
    __syncthreads();
    float acc = col[t];
    #pragma unroll 8
    for (int m = 0; m < DD; m++) acc += Wpos[t * DD + m] * col[m];
    weff[j * DD + t] = __float2half_rn(acc);
    if (t == 0) {
        float s = 0.f;
        for (int m = 0; m < DD; m++) s += (bpos[m] + bdeg[m]) * col[m];
        beff[j] = s + bb[jj];
    }
    if (t == 1) {
        float s = 0.f;
        for (int m = 0; m < DD; m++) s += Wdeg[m] * col[m];
        wdegeff[j] = s;
    }
}

// convert + transpose BOTH layers' weights to fp16 [N][K]
__global__ void k_cvtw(const float* __restrict__ Wo, const float* __restrict__ W1,
                       const float* __restrict__ W2, __half* wo, __half* w1, __half* w2) {
    int i = blockIdx.x * blockDim.x + threadIdx.x;
    int l = blockIdx.y;
    const float* Wo_l = Wo + (size_t)l * DD * DD;
    const float* W1_l = W1 + (size_t)l * DD * FFD;
    const float* W2_l = W2 + (size_t)l * FFD * DD;
    __half* wo_l = wo + (size_t)l * DD * DD;
    __half* w1_l = w1 + (size_t)l * FFD * DD;
    __half* w2_l = w2 + (size_t)l * DD * FFD;
    if (i < DD * DD) {
        int k = i / DD, n = i % DD;
        wo_l[n * DD + k] = __float2half_rn(Wo_l[i]);
    }
    if (i < DD * FFD) {
        int k1 = i / FFD, n1 = i % FFD;
        w1_l[n1 * DD + k1] = __float2half_rn(W1_l[i]);
        int k2 = i / DD, n2 = i % DD;
        w2_l[n2 * FFD + k2] = __float2half_rn(W2_l[i]);
    }
}

// ---------------- LayerNorm (warp per node, fp16 output) -----------------------
__global__ void k_layernorm(const float* __restrict__ x, const float* __restrict__ g,
                            const float* __restrict__ b, __half* __restrict__ out) {
    int node = (blockIdx.x * blockDim.x + threadIdx.x) >> 5;
    int lane = threadIdx.x & 31;
    if (node >= NN) return;
    const float4 v = *(const float4*)(x + (long)node * DD + lane * 4);
    float s = v.x + v.y + v.z + v.w;
    #pragma unroll
    for (int o = 16; o > 0; o >>= 1) s += __shfl_xor_sync(0xffffffffu, s, o);
    float mu = s * (1.0f / DD);
    float dx = v.x - mu, dy = v.y - mu, dz = v.z - mu, dw = v.w - mu;
    float q = dx * dx + dy * dy + dz * dz + dw * dw;
    #pragma unroll
    for (int o = 16; o > 0; o >>= 1) q += __shfl_xor_sync(0xffffffffu, q, o);
    float rs = rsqrtf(q * (1.0f / DD) + 1e-5f);
    const float4 gg = *(const float4*)(g + lane * 4);
    const float4 bb = *(const float4*)(b + lane * 4);
    __half2 h0 = __floats2half2_rn(dx * rs * gg.x + bb.x, dy * rs * gg.y + bb.y);
    __half2 h1 = __floats2half2_rn(dz * rs * gg.z + bb.z, dw * rs * gg.w + bb.w);
    uint2 u = make_uint2(h2u(h0), h2u(h1));
    *(uint2*)(out + (long)node * DD + lane * 4) = u;
}

// ---------------- 3-stage pipelined fp16 GEMM (m16n8k16, fp32 accum) -----------
// mode 0: half out  = acc + bias + degn[i]*wdeg[j]
// mode 1: float out = acc + bias + C
// mode 2: half out  = gelu(acc + bias)
// mode 3: float C += acc + bias;  half xnout = LayerNorm(rows of C)  [NT==8, N==128]
#define BKH 64
#define LDH 72
#define NSTAGE 3
#define ASTAGE_H (BM * LDH)

__device__ __forceinline__ unsigned smemu32(const void* p) {
    return (unsigned)__cvta_generic_to_shared(p);
}

template<int NT>
__global__ __launch_bounds__(256, 2) void gemm_hf(
    const __half* __restrict__ A, const __half* __restrict__ Bt, void* Cv,
    const float* __restrict__ bias, const float* __restrict__ wdegv,
    const float* __restrict__ degn, const float* __restrict__ lng,
    const float* __restrict__ lnb, __half* __restrict__ xnout,
    int M, int N, int K, int mode) {
    constexpr int BN = NT * 16;
    constexpr int BSTAGE_H = BN * LDH;
    extern __shared__ __half sm[];
    __half* As = sm;
    __half* Bs = sm + NSTAGE * ASTAGE_H;

    const int tid  = threadIdx.x;
    const int warp = tid >> 5;
    const int lane = tid & 31;
    const int wm = warp >> 1;
    const int wn = warp & 1;
    const int g  = lane >> 2;
    const int q  = lane & 3;
    const int rowBase = blockIdx.y * BM;
    const int colBase = blockIdx.x * BN;

    float acc[2][NT][4];
    #pragma unroll
    for (int i = 0; i < 2; i++)
        #pragma unroll
        for (int j = 0; j < NT; j++)
            #pragma unroll
            for (int k = 0; k < 4; k++) acc[i][j][k] = 0.0f;

    const int nk = K / BKH;

    auto loadA = [&](int s, int k0) {
        #pragma unroll
        for (int i = 0; i < 4; i++) {
            int idx = tid + i * 256;
            int r = idx >> 3, c = (idx & 7) * 8;
            int grow = rowBase + r;
            const __half* src = A + (long)(grow < M ? grow : M - 1) * K + k0 + c;
            int sz = (grow < M) ? 16 : 0;
            asm volatile("cp.async.cg.shared.global [%0], [%1], 16, %2;"
                         :: "r"(smemu32(As + s * ASTAGE_H + r * LDH + c)), "l"(src), "r"(sz));
        }
    };
    auto loadB = [&](int s, int k0) {
        #pragma unroll
        for (int i = 0; i < NT / 2; i++) {
            int idx = tid + i * 256;
            int n = idx >> 3, c = (idx & 7) * 8;
            const __half* src = Bt + (long)(colBase + n) * K + k0 + c;
            asm volatile("cp.async.cg.shared.global [%0], [%1], 16;"
                         :: "r"(smemu32(Bs + s * BSTAGE_H + n * LDH + c)), "l"(src));
        }
    };

    unsigned aBase = smemu32(As);
    unsigned bBase = smemu32(Bs);
    unsigned offA[2], offB[NT / 2];
    #pragma unroll
    for (int mt = 0; mt < 2; mt++) {
        int row = wm * 32 + mt * 16 + (lane & 15);
        int kh  = (lane >> 4) << 3;
        offA[mt] = (unsigned)((row * LDH + kh) * 2);
    }
    #pragma unroll
    for (int p = 0; p < NT / 2; p++) {
        int row = wn * (NT * 8) + p * 16 + ((lane >> 4) << 3) + (lane & 7);
        int kh  = ((lane >> 3) & 1) << 3;
        offB[p] = (unsigned)((row * LDH + kh) * 2);
    }

    loadA(0, 0); loadB(0, 0);
    asm volatile("cp.async.commit_group;");
    if (nk > 1) { loadA(1, BKH); loadB(1, BKH); }
    asm volatile("cp.async.commit_group;");

    int buf = 0;
    for (int kb = 0; kb < nk; kb++) {
        asm volatile("cp.async.wait_group 1;");
        __syncthreads();
        if (kb + 2 < nk) {
            int s = (kb + 2) % NSTAGE;
            loadA(s, (kb + 2) * BKH);
            loadB(s, (kb + 2) * BKH);
        }
        asm volatile("cp.async.commit_group;");

        unsigned aStage = aBase + buf * (ASTAGE_H * 2);
        unsigned bStage = bBase + buf * (BSTAGE_H * 2);
        #pragma unroll
        for (int kk = 0; kk < BKH; kk += 16) {
            unsigned a_frag[2][4];
            #pragma unroll
            for (int mt = 0; mt < 2; mt++) {
                asm volatile("ldmatrix.sync.aligned.m8n8.x4.shared.b16 "
                             "{%0,%1,%2,%3}, [%4];"
                             : "=r"(a_frag[mt][0]), "=r"(a_frag[mt][1]),
                               "=r"(a_frag[mt][2]), "=r"(a_frag[mt][3])
                             : "r"(aStage + offA[mt] + kk * 2));
            }
            unsigned b_frag[NT][2];
            #pragma unroll
            for (int p = 0; p < NT / 2; p++) {
                asm volatile("ldmatrix.sync.aligned.m8n8.x4.shared.b16 "
                             "{%0,%1,%2,%3}, [%4];"
                             : "=r"(b_frag[2 * p][0]), "=r"(b_frag[2 * p][1]),
                               "=r"(b_frag[2 * p + 1][0]), "=r"(b_frag[2 * p + 1][1])
                             : "r"(bStage + offB[p] + kk * 2));
            }
            #pragma unroll
            for (int mt = 0; mt < 2; mt++)
                #pragma unroll
                for (int nt = 0; nt < NT; nt++) {
                    asm volatile(
                        "mma.sync.aligned.m16n8k16.row.col.f32.f16.f16.f32 "
                        "{%0,%1,%2,%3}, {%4,%5,%6,%7}, {%8,%9}, {%0,%1,%2,%3};"
                        : "+f"(acc[mt][nt][0]), "+f"(acc[mt][nt][1]),
                          "+f"(acc[mt][nt][2]), "+f"(acc[mt][nt][3])
                        : "r"(a_frag[mt][0]), "r"(a_frag[mt][1]),
                          "r"(a_frag[mt][2]), "r"(a_frag[mt][3]),
                          "r"(b_frag[nt][0]), "r"(b_frag[nt][1]));
                }
        }
        __syncthreads();
        buf = (buf + 1 == NSTAGE) ? 0 : buf + 1;
    }

    if (mode == 3) {
        if constexpr (NT == 8) {
            float* red = (float*)sm;
            #pragma unroll
            for (int mt = 0; mt < 2; mt++) {
                #pragma unroll
                for (int half = 0; half < 2; half++) {
                    int gr = rowBase + wm * 32 + mt * 16 + g + half * 8;
                    float ls = 0.f, lq = 0.f;
                    if (gr < M) {
                        #pragma unroll
                        for (int nt = 0; nt < NT; nt++) {
                            int gc = wn * 64 + nt * 8 + q * 2;
                            float* cp = (float*)Cv + (long)gr * N + gc;
                            float2 old = *(const float2*)cp;
                            float v0 = acc[mt][nt][half * 2 + 0] + bias[gc] + old.x;
                            float v1 = acc[mt][nt][half * 2 + 1] + bias[gc + 1] + old.y;
                            *(float2*)cp = make_float2(v0, v1);
                            acc[mt][nt][half * 2 + 0] = v0;
                            acc[mt][nt][half * 2 + 1] = v1;
                            ls += v0 + v1;
                            lq += v0 * v0 + v1 * v1;
                        }
                    }
                    ls += __shfl_xor_sync(0xffffffffu, ls, 1);
                    ls += __shfl_xor_sync(0xffffffffu, ls, 2);
                    lq += __shfl_xor_sync(0xffffffffu, lq, 1);
                    lq += __shfl_xor_sync(0xffffffffu, lq, 2);
                    if (q == 0 && gr < M) {
                        int idx = (((wm * 2 + mt) * 2 + half) * 8 + g) * 2 + wn;
                        red[idx] = ls;
                        red[512 + idx] = lq;
                    }
                }
            }
            __syncthreads();
            #pragma unroll
            for (int mt = 0; mt < 2; mt++) {
                #pragma unroll
                for (int half = 0; half < 2; half++) {
                    int gr = rowBase + wm * 32 + mt * 16 + g + half * 8;
                    if (gr >= M) continue;
                    int i0 = (((wm * 2 + mt) * 2 + half) * 8 + g) * 2;
                    float ts = red[i0] + red[i0 + 1];
                    float tq = red[512 + i0] + red[512 + i0 + 1];
                    float mu = ts * (1.0f / 128.0f);
                    float var = tq * (1.0f / 128.0f) - mu * mu;
                    float rsg = rsqrtf(var + 1e-5f);
                    #pragma unroll
                    for (int nt = 0; nt < NT; nt++) {
                        int gc = wn * 64 + nt * 8 + q * 2;
                        float v0 = (acc[mt][nt][half * 2 + 0] - mu) * rsg * lng[gc] + lnb[gc];
                        float v1 = (acc[mt][nt][half * 2 + 1] - mu) * rsg * lng[gc + 1] + lnb[gc + 1];
                        __half* xp = xnout + (long)gr * N + gc;
                        *(__half2*)xp = __floats2half2_rn(v0, v1);
                    }
                }
            }
        }
        return;
    }

    #pragma unroll
    for (int mt = 0; mt < 2; mt++) {
        #pragma unroll
        for (int half = 0; half < 2; half++) {
            int gr = rowBase + wm * 32 + mt * 16 + g + half * 8;
            if (gr >= M) continue;
            float dn = (mode == 0) ? degn[gr] : 0.0f;
            #pragma unroll
            for (int nt = 0; nt < NT; nt++) {
                int gc = colBase + wn * (NT * 8) + nt * 8 + q * 2;
                float v0 = acc[mt][nt][half * 2 + 0] + bias[gc];
                float v1 = acc[mt][nt][half * 2 + 1] + bias[gc + 1];
                if (mode == 1) {
                    float* cp = (float*)Cv + (long)gr * N + gc;
                    float2 old = *(const float2*)cp;
                    *(float2*)cp = make_float2(v0 + old.x, v1 + old.y);
                } else {
                    if (mode == 0) {
                        v0 += dn * wdegv[gc];
                        v1 += dn * wdegv[gc + 1];
                    } else {
                        v0 = 0.5f * v0 * (1.0f + erff(v0 * 0.70710678118654752f));
                        v1 = 0.5f * v1 * (1.0f + erff(v1 * 0.70710678118654752f));
                    }
                    __half* cp = (__half*)Cv + (long)gr * N + gc;
                    *(__half2*)cp = __floats2half2_rn(v0, v1);
                }
            }
        }
    }
}
#define SMEM8 (NSTAGE * (ASTAGE_H + 128 * LDH) * (int)sizeof(__half))
#define SMEM4 (NSTAGE * (ASTAGE_H + 64 * LDH) * (int)sizeof(__half))

// ---------------- fused single-pass CSR attention (warp per dst node) ----------
__device__ __forceinline__ float4 ld4h(const __half* p) {
    uint2 u = *(const uint2*)p;
    __half2 h0, h1;
    memcpy(&h0, &u.x, 4);
    memcpy(&h1, &u.y, 4);
    float2 a = __half22float2(h0);
    float2 b = __half22float2(h1);
    return make_float4(a.x, a.y, b.x, b.y);
}

__global__ __launch_bounds__(256) void k_attn(
    const int* __restrict__ off, const int* __restrict__ csr,
    const __half* __restrict__ qkv, __half* __restrict__ aggr) {
    int w = (blockIdx.x * blockDim.x + threadIdx.x) >> 5;
    int lane = threadIdx.x & 31;
    if (w >= NN) return;
    const int beg = off[w], end = off[w + 1];

    float4 qv = ld4h(qkv + (long)w * 384 + lane * 4);

    float s_acc = 0.0f;
    float ax = 0.f, ay = 0.f, az = 0.f, aw = 0.f;
    int e = beg;
    for (; e + 1 < end; e += 2) {
        int s0 = csr[e], s1 = csr[e + 1];
        float4 k0 = ld4h(qkv + (long)s0 * 384 + 128 + lane * 4);
        float4 k1 = ld4h(qkv + (long)s1 * 384 + 128 + lane * 4);
        float4 v0 = ld4h(qkv + (long)s0 * 384 + 256 + lane * 4);
        float4 v1 = ld4h(qkv + (long)s1 * 384 + 256 + lane * 4);
        float p0 = qv.x * k0.x + qv.y * k0.y + qv.z * k0.z + qv.w * k0.w;
        float p1 = qv.x * k1.x + qv.y * k1.y + qv.z * k1.z + qv.w * k1.w;
        p0 += __shfl_xor_sync(0xffffffffu, p0, 1);
        p0 += __shfl_xor_sync(0xffffffffu, p0, 2);
        p1 += __shfl_xor_sync(0xffffffffu, p1, 1);
        p1 += __shfl_xor_sync(0xffffffffu, p1, 2);
        float ex0 = __expf(fminf(fmaxf(p0 * 0.25f, -50.f), 50.f));
        float ex1 = __expf(fminf(fmaxf(p1 * 0.25f, -50.f), 50.f));
        s_acc += ex0 + ex1;
        ax += ex0 * v0.x + ex1 * v1.x;
        ay += ex0 * v0.y + ex1 * v1.y;
        az += ex0 * v0.z + ex1 * v1.z;
        aw += ex0 * v0.w + ex1 * v1.w;
    }
    if (e < end) {
        int s0 = csr[e];
        float4 k0 = ld4h(qkv + (long)s0 * 384 + 128 + lane * 4);
        float4 v0 = ld4h(qkv + (long)s0 * 384 + 256 + lane * 4);
        float p0 = qv.x * k0.x + qv.y * k0.y + qv.z * k0.z + qv.w * k0.w;
        p0 += __shfl_xor_sync(0xffffffffu, p0, 1);
        p0 += __shfl_xor_sync(0xffffffffu, p0, 2);
        float ex0 = __expf(fminf(fmaxf(p0 * 0.25f, -50.f), 50.f));
        s_acc += ex0;
        ax += ex0 * v0.x;
        ay += ex0 * v0.y;
        az += ex0 * v0.z;
        aw += ex0 * v0.w;
    }
    float rs = 1.0f / (s_acc + 1e-16f);
    __half2 h0 = __floats2half2_rn(ax * rs, ay * rs);
    __half2 h1 = __floats2half2_rn(az * rs, aw * rs);
    uint2 u = make_uint2(h2u(h0), h2u(h1));
    *(uint2*)(aggr + (long)w * DD + lane * 4) = u;
}

// ---------------- driver --------------------------------------------------------
extern "C" void kernel_launch(void* const* d_in, const int* in_sizes, int n_in,
                              void* d_out, int out_size) {
    const float* x    = (const float*)d_in[0];
    const int*   ei   = (const int*)d_in[1];
    const float* Wq   = (const float*)d_in[2];
    const float* Wk   = (const float*)d_in[3];
    const float* Wv   = (const float*)d_in[4];
    const float* Wo   = (const float*)d_in[5];
    const float* Wpos = (const float*)d_in[6];
    const float* Wdeg = (const float*)d_in[7];
    const float* W1   = (const float*)d_in[8];
    const float* W2   = (const float*)d_in[9];
    const float* bq   = (const float*)d_in[10];
    const float* bk   = (const float*)d_in[11];
    const float* bv   = (const float*)d_in[12];
    const float* bo   = (const float*)d_in[13];
    const float* bpos = (const float*)d_in[14];
    const float* bdeg = (const float*)d_in[15];
    const float* ln1b = (const float*)d_in[16];
    const float* ln2b = (const float*)d_in[17];
    const float* b1   = (const float*)d_in[18];
    const float* b2   = (const float*)d_in[19];
    const float* ln1g = (const float*)d_in[20];
    const float* ln2g = (const float*)d_in[21];
    float* xbuf = (float*)d_out;

    __half *xn, *qkv, *aggr, *hb, *weff, *wo, *w1, *w2;
    float *deg, *degn, *beff, *wde;
    int *ddeg, *off, *cur, *csr;
    double* stats;
    cudaGetSymbolAddress((void**)&xn,    g_xn);
    cudaGetSymbolAddress((void**)&qkv,   g_qkv);
    cudaGetSymbolAddress((void**)&aggr,  g_aggr);
    cudaGetSymbolAddress((void**)&hb,    g_h);
    cudaGetSymbolAddress((void**)&deg,   g_deg);
    cudaGetSymbolAddress((void**)&degn,  g_degn);
    cudaGetSymbolAddress((void**)&weff,  g_weff);
    cudaGetSymbolAddress((void**)&beff,  g_beff);
    cudaGetSymbolAddress((void**)&wde,   g_wdegeff);
    cudaGetSymbolAddress((void**)&wo,    g_wo);
    cudaGetSymbolAddress((void**)&w1,    g_w1);
    cudaGetSymbolAddress((void**)&w2,    g_w2);
    cudaGetSymbolAddress((void**)&ddeg,  g_ddeg);
    cudaGetSymbolAddress((void**)&off,   g_off);
    cudaGetSymbolAddress((void**)&cur,   g_cur);
    cudaGetSymbolAddress((void**)&csr,   g_csr);
    cudaGetSymbolAddress((void**)&stats, g_stats);

    cudaFuncSetAttribute((void*)gemm_hf<8>,
                         cudaFuncAttributeMaxDynamicSharedMemorySize, SMEM8);
    cudaFuncSetAttribute((void*)gemm_hf<4>,
                         cudaFuncAttributeMaxDynamicSharedMemorySize, SMEM4);

    // side streams + fork/join events (created once, on the first uncaptured call)
    static cudaStream_t s1 = nullptr, s2 = nullptr;
    static cudaEvent_t evRoot, evW, evC, evD, evCSR;
    if (!s1) {
        cudaStreamCreateWithFlags(&s1, cudaStreamNonBlocking);
        cudaStreamCreateWithFlags(&s2, cudaStreamNonBlocking);
        cudaEventCreateWithFlags(&evRoot, cudaEventDisableTiming);
        cudaEventCreateWithFlags(&evW,    cudaEventDisableTiming);
        cudaEventCreateWithFlags(&evC,    cudaEventDisableTiming);
        cudaEventCreateWithFlags(&evD,    cudaEventDisableTiming);
        cudaEventCreateWithFlags(&evCSR,  cudaEventDisableTiming);
    }

    const int rowBlocks = (NN + BM - 1) / BM;
    const int lnBlocks  = (NN + 7) / 8;
    const int nodeWarpBlocks = (NN + 7) / 8;

    // fork
    cudaEventRecord(evRoot, 0);
    cudaStreamWaitEvent(s1, evRoot, 0);
    cudaStreamWaitEvent(s2, evRoot, 0);

    // s1: all weight preprocessing (both layers)
    for (int l = 0; l < LL; l++) {
        k_weff<<<3 * DD, DD, 0, s1>>>(
            Wq + (size_t)l * DD * DD, Wk + (size_t)l * DD * DD,
            Wv + (size_t)l * DD * DD, Wpos + (size_t)l * DD * DD,
            Wdeg + (size_t)l * DD, bq + l * DD, bk + l * DD, bv + l * DD,
            bpos + l * DD, bdeg + l * DD,
            weff + (size_t)l * 3 * DD * DD, beff + l * 3 * DD, wde + l * 3 * DD);
    }
    cudaEventRecord(evW, s1);
    k_cvtw<<<dim3((DD * FFD + 255) / 256, LL), 256, 0, s1>>>(Wo, W1, W2, wo, w1, w2);
    cudaEventRecord(evC, s1);

    // s2: degree stats + CSR build
    k_prep<<<(NN + 255) / 256, 256, 0, s2>>>(deg, ddeg, stats);
    k_degcount2<<<(EE + 255) / 256, 256, 0, s2>>>(ei, deg, ddeg);
    k_deg_reduce<<<148, 256, 0, s2>>>(deg, stats);
    k_deg_norm<<<(NN + 255) / 256, 256, 0, s2>>>(deg, stats, degn);
    cudaEventRecord(evD, s2);
    k_scan<<<1, 1024, 0, s2>>>(ddeg, off, cur, csr);
    k_csr_scatter<<<(EE + 255) / 256, 256, 0, s2>>>(ei, cur, csr);
    cudaEventRecord(evCSR, s2);

    // main stream: x copy + LN1, then join
    cudaMemcpyAsync(xbuf, x, (size_t)NN * DD * sizeof(float),
                    cudaMemcpyDeviceToDevice, 0);
    k_layernorm<<<lnBlocks, 256>>>(xbuf, ln1g, ln1b, xn);
    cudaStreamWaitEvent(0, evW, 0);
    cudaStreamWaitEvent(0, evD, 0);
    gemm_hf<8><<<dim3(3, rowBlocks), 256, SMEM8>>>(
        xn, weff, qkv, beff, wde, degn, nullptr, nullptr, nullptr,
        NN, 3 * DD, DD, 0);
    cudaStreamWaitEvent(0, evCSR, 0);
    cudaStreamWaitEvent(0, evC, 0);

    for (int l = 0; l < LL; l++) {
        __half* wo_l = wo + (size_t)l * DD * DD;
        __half* w1_l = w1 + (size_t)l * FFD * DD;
        __half* w2_l = w2 + (size_t)l * DD * FFD;
        k_attn<<<nodeWarpBlocks, 256>>>(off, csr, qkv, aggr);
        gemm_hf<8><<<dim3(1, rowBlocks), 256, SMEM8>>>(
            aggr, wo_l, xbuf, bo + l * DD, nullptr, nullptr,
            ln2g + l * DD, ln2b + l * DD, xn, NN, DD, DD, 3);
        gemm_hf<8><<<dim3(4, rowBlocks), 256, SMEM8>>>(
            xn, w1_l, hb, b1 + l * FFD, nullptr, nullptr, nullptr, nullptr, nullptr,
            NN, FFD, DD, 2);
        if (l + 1 < LL) {
            int n = l + 1;
            gemm_hf<8><<<dim3(1, rowBlocks), 256, SMEM8>>>(
                hb, w2_l, xbuf, b2 + l * DD, nullptr, nullptr,
                ln1g + n * DD, ln1b + n * DD, xn, NN, DD, FFD, 3);
            gemm_hf<8><<<dim3(3, rowBlocks), 256, SMEM8>>>(
                xn, weff + (size_t)n * 3 * DD * DD, qkv, beff + n * 3 * DD,
                wde + n * 3 * DD, degn, nullptr, nullptr, nullptr,
                NN, 3 * DD, DD, 0);
        } else {
            gemm_hf<4><<<dim3(2, rowBlocks), 256, SMEM4>>>(
                hb, w2_l, xbuf, b2 + l * DD, nullptr, nullptr, nullptr, nullptr, nullptr,
                NN, DD, FFD, 1);
        }
    }
}

// round 15
// speedup vs baseline: 1.1726x; 1.0560x over previous
#include <cuda_runtime.h>
#include <cuda_fp16.h>
#include <math.h>

#define NN 50000
#define EE 500000
#define DD 128
#define HH 8
#define LL 2
#define FFD 512
#define NE (EE + NN)
#define BM 128

// row-half split: H0 = rows [0, 25088), H1 = [25088, 50000)
#define RB0 196
#define RB1 195
#define SPLIT (RB0 * BM)      // 25088
#define NB0 (SPLIT / 8)       // 3136 warp-blocks
#define NB1 ((NN - SPLIT + 7) / 8)

// ---------------- scratch ----------------------------------------------------
__device__ __align__(16) __half g_xn[NN * DD];
__device__ __align__(16) __half g_qkv[NN * 3 * DD];
__device__ __align__(16) __half g_aggr[NN * DD];
__device__ __align__(16) __half g_h[NN * FFD];
__device__ float  g_deg[NN];
__device__ float  g_degn[NN];
__device__ double g_stats[2];
__device__ __align__(16) __half g_weff[LL * 3 * DD * DD];
__device__ float  g_beff[LL * 3 * DD];
__device__ float  g_wdegeff[LL * 3 * DD];
__device__ __align__(16) __half g_wo[LL * DD * DD];
__device__ __align__(16) __half g_w1[LL * FFD * DD];
__device__ __align__(16) __half g_w2[LL * DD * FFD];
__device__ int    g_ddeg[NN];
__device__ int    g_off[NN + 1];
__device__ int    g_cur[NN];
__device__ int    g_csr[NE];

__device__ __forceinline__ unsigned h2u(__half2 h) {
    unsigned u;
    memcpy(&u, &h, 4);
    return u;
}

// ---------------- prep --------------------------------------------------------
__global__ void k_prep(float* deg, int* ddeg, double* st) {
    int i = blockIdx.x * blockDim.x + threadIdx.x;
    if (i < NN) { deg[i] = 1.f; ddeg[i] = 1; }
    if (i == 0) { st[0] = 0.0; st[1] = 0.0; }
}

// ---------------- degree + CSR build -------------------------------------------
__global__ void k_degcount2(const int* __restrict__ ei, float* deg, int* ddeg) {
    int e = blockIdx.x * blockDim.x + threadIdx.x;
    if (e < EE) {
        atomicAdd(&deg[ei[e]], 1.0f);
        atomicAdd(&ddeg[ei[EE + e]], 1);
    }
}
__global__ void k_scan(const int* __restrict__ ddeg, int* __restrict__ off,
                       int* __restrict__ cur, int* __restrict__ csr) {
    __shared__ int wsum[32];
    __shared__ int carry;
    int t = threadIdx.x, lane = t & 31, wid = t >> 5;
    if (t == 0) { carry = 0; off[0] = 0; }
    __syncthreads();
    for (int base = 0; base < NN; base += 1024) {
        int i = base + t;
        int v = (i < NN) ? ddeg[i] : 0;
        int s = v;
        #pragma unroll
        for (int o = 1; o < 32; o <<= 1) {
            int u = __shfl_up_sync(0xffffffffu, s, o);
            if (lane >= o) s += u;
        }
        if (lane == 31) wsum[wid] = s;
        __syncthreads();
        if (wid == 0) {
            int ws = wsum[lane];
            #pragma unroll
            for (int o = 1; o < 32; o <<= 1) {
                int u = __shfl_up_sync(0xffffffffu, ws, o);
                if (lane >= o) ws += u;
            }
            wsum[lane] = ws;
        }
        __syncthreads();
        int add = (wid > 0) ? wsum[wid - 1] : 0;
        int incl = s + add + carry;
        if (i < NN) {
            off[i + 1] = incl;
            int oi = incl - v;
            csr[oi] = i;
            cur[i] = oi + 1;
        }
        __syncthreads();
        if (t == 1023) carry = incl;
        __syncthreads();
    }
}
__global__ void k_csr_scatter(const int* __restrict__ ei, int* cur, int* csr) {
    int e = blockIdx.x * blockDim.x + threadIdx.x;
    if (e >= EE) return;
    int dst = ei[EE + e];
    int pos = atomicAdd(&cur[dst], 1);
    csr[pos] = ei[e];
}

__global__ void k_deg_reduce(const float* __restrict__ deg, double* st) {
    __shared__ double ss[256], sq[256];
    int t = threadIdx.x;
    double s = 0.0, q = 0.0;
    for (int i = blockIdx.x * blockDim.x + t; i < NN; i += gridDim.x * blockDim.x) {
        double d = (double)deg[i];
        s += d; q += d * d;
    }
    ss[t] = s; sq[t] = q;
    __syncthreads();
    for (int o = 128; o > 0; o >>= 1) {
        if (t < o) { ss[t] += ss[t + o]; sq[t] += sq[t + o]; }
        __syncthreads();
    }
    if (t == 0) { atomicAdd(&st[0], ss[0]); atomicAdd(&st[1], sq[0]); }
}
__global__ void k_deg_norm(const float* __restrict__ deg, const double* __restrict__ st,
                           float* __restrict__ degn) {
    int i = blockIdx.x * blockDim.x + threadIdx.x;
    if (i >= NN) return;
    double mean = st[0] / (double)NN;
    double var  = (st[1] - st[0] * st[0] / (double)NN) / (double)(NN - 1);
    float  sd   = (float)sqrt(var);
    degn[i] = (deg[i] - (float)mean) / (sd + 1e-6f);
}

// ---------------- folded effective weights (fp16, TRANSPOSED [N][K]) -----------
__global__ void k_weff(const float* __restrict__ Wq, const float* __restrict__ Wk,
                       const float* __restrict__ Wv, const float* __restrict__ Wpos,
                       const float* __restrict__ Wdeg,
                       const float* __restrict__ bq, const float* __restrict__ bk,
                       const float* __restrict__ bv, const float* __restrict__ bpos,
                       const float* __restrict__ bdeg,
                       __half* __restrict__ weff, float* __restrict__ beff,
                       float* __restrict__ wdegeff) {
    int j = blockIdx.x;
    int t = threadIdx.x;
    const float* W  = (j < DD) ? Wq : ((j < 2 * DD) ? Wk : Wv);
    const float* bb = (j < DD) ? bq : ((j < 2 * DD) ? bk : bv);
    int jj = j & (DD - 1);
    __shared__ float col[DD];
    col[t] = W[t * DD + jj];
    __syncthreads();
    float acc = col[t];
    #pragma unroll 8
    for (int m = 0; m < DD; m++) acc += Wpos[t * DD + m] * col[m];
    weff[j * DD + t] = __float2half_rn(acc);
    if (t == 0) {
        float s = 0.f;
        for (int m = 0; m < DD; m++) s += (bpos[m] + bdeg[m]) * col[m];
        beff[j] = s + bb[jj];
    }
    if (t == 1) {
        float s = 0.f;
        for (int m = 0; m < DD; m++) s += Wdeg[m] * col[m];
        wdegeff[j] = s;
    }
}

// convert + transpose BOTH layers' weights to fp16 [N][K]
__global__ void k_cvtw(const float* __restrict__ Wo, const float* __restrict__ W1,
                       const float* __restrict__ W2, __half* wo, __half* w1, __half* w2) {
    int i = blockIdx.x * blockDim.x + threadIdx.x;
    int l = blockIdx.y;
    const float* Wo_l = Wo + (size_t)l * DD * DD;
    const float* W1_l = W1 + (size_t)l * DD * FFD;
    const float* W2_l = W2 + (size_t)l * FFD * DD;
    __half* wo_l = wo + (size_t)l * DD * DD;
    __half* w1_l = w1 + (size_t)l * FFD * DD;
    __half* w2_l = w2 + (size_t)l * DD * FFD;
    if (i < DD * DD) {
        int k = i / DD, n = i % DD;
        wo_l[n * DD + k] = __float2half_rn(Wo_l[i]);
    }
    if (i < DD * FFD) {
        int k1 = i / FFD, n1 = i % FFD;
        w1_l[n1 * DD + k1] = __float2half_rn(W1_l[i]);
        int k2 = i / DD, n2 = i % DD;
        w2_l[n2 * FFD + k2] = __float2half_rn(W2_l[i]);
    }
}

// ---------------- LayerNorm (warp per node, fp16 output) -----------------------
__global__ void k_layernorm(const float* __restrict__ x, const float* __restrict__ g,
                            const float* __restrict__ b, __half* __restrict__ out) {
    int node = (blockIdx.x * blockDim.x + threadIdx.x) >> 5;
    int lane = threadIdx.x & 31;
    if (node >= NN) return;
    const float4 v = *(const float4*)(x + (long)node * DD + lane * 4);
    float s = v.x + v.y + v.z + v.w;
    #pragma unroll
    for (int o = 16; o > 0; o >>= 1) s += __shfl_xor_sync(0xffffffffu, s, o);
    float mu = s * (1.0f / DD);
    float dx = v.x - mu, dy = v.y - mu, dz = v.z - mu, dw = v.w - mu;
    float q = dx * dx + dy * dy + dz * dz + dw * dw;
    #pragma unroll
    for (int o = 16; o > 0; o >>= 1) q += __shfl_xor_sync(0xffffffffu, q, o);
    float rs = rsqrtf(q * (1.0f / DD) + 1e-5f);
    const float4 gg = *(const float4*)(g + lane * 4);
    const float4 bb = *(const float4*)(b + lane * 4);
    __half2 h0 = __floats2half2_rn(dx * rs * gg.x + bb.x, dy * rs * gg.y + bb.y);
    __half2 h1 = __floats2half2_rn(dz * rs * gg.z + bb.z, dw * rs * gg.w + bb.w);
    uint2 u = make_uint2(h2u(h0), h2u(h1));
    *(uint2*)(out + (long)node * DD + lane * 4) = u;
}

// ---------------- 3-stage pipelined fp16 GEMM (m16n8k16, fp32 accum) -----------
// mode 0: half out  = acc + bias + degn[i]*wdeg[j]
// mode 1: float out = acc + bias + C
// mode 2: half out  = gelu(acc + bias)
// mode 3: float C += acc + bias;  half xnout = LayerNorm(rows of C)  [NT==8, N==128]
#define BKH 64
#define LDH 72
#define NSTAGE 3
#define ASTAGE_H (BM * LDH)

__device__ __forceinline__ unsigned smemu32(const void* p) {
    return (unsigned)__cvta_generic_to_shared(p);
}

template<int NT>
__global__ __launch_bounds__(256, 2) void gemm_hf(
    const __half* __restrict__ A, const __half* __restrict__ Bt, void* Cv,
    const float* __restrict__ bias, const float* __restrict__ wdegv,
    const float* __restrict__ degn, const float* __restrict__ lng,
    const float* __restrict__ lnb, __half* __restrict__ xnout,
    int M, int N, int K, int mode, int rowOff) {
    constexpr int BN = NT * 16;
    constexpr int BSTAGE_H = BN * LDH;
    extern __shared__ __half sm[];
    __half* As = sm;
    __half* Bs = sm + NSTAGE * ASTAGE_H;

    const int tid  = threadIdx.x;
    const int warp = tid >> 5;
    const int lane = tid & 31;
    const int wm = warp >> 1;
    const int wn = warp & 1;
    const int g  = lane >> 2;
    const int q  = lane & 3;
    const int rowBase = (blockIdx.y + rowOff) * BM;
    const int colBase = blockIdx.x * BN;

    float acc[2][NT][4];
    #pragma unroll
    for (int i = 0; i < 2; i++)
        #pragma unroll
        for (int j = 0; j < NT; j++)
            #pragma unroll
            for (int k = 0; k < 4; k++) acc[i][j][k] = 0.0f;

    const int nk = K / BKH;

    auto loadA = [&](int s, int k0) {
        #pragma unroll
        for (int i = 0; i < 4; i++) {
            int idx = tid + i * 256;
            int r = idx >> 3, c = (idx & 7) * 8;
            int grow = rowBase + r;
            const __half* src = A + (long)(grow < M ? grow : M - 1) * K + k0 + c;
            int sz = (grow < M) ? 16 : 0;
            asm volatile("cp.async.cg.shared.global [%0], [%1], 16, %2;"
                         :: "r"(smemu32(As + s * ASTAGE_H + r * LDH + c)), "l"(src), "r"(sz));
        }
    };
    auto loadB = [&](int s, int k0) {
        #pragma unroll
        for (int i = 0; i < NT / 2; i++) {
            int idx = tid + i * 256;
            int n = idx >> 3, c = (idx & 7) * 8;
            const __half* src = Bt + (long)(colBase + n) * K + k0 + c;
            asm volatile("cp.async.cg.shared.global [%0], [%1], 16;"
                         :: "r"(smemu32(Bs + s * BSTAGE_H + n * LDH + c)), "l"(src));
        }
    };

    unsigned aBase = smemu32(As);
    unsigned bBase = smemu32(Bs);
    unsigned offA[2], offB[NT / 2];
    #pragma unroll
    for (int mt = 0; mt < 2; mt++) {
        int row = wm * 32 + mt * 16 + (lane & 15);
        int kh  = (lane >> 4) << 3;
        offA[mt] = (unsigned)((row * LDH + kh) * 2);
    }
    #pragma unroll
    for (int p = 0; p < NT / 2; p++) {
        int row = wn * (NT * 8) + p * 16 + ((lane >> 4) << 3) + (lane & 7);
        int kh  = ((lane >> 3) & 1) << 3;
        offB[p] = (unsigned)((row * LDH + kh) * 2);
    }

    loadA(0, 0); loadB(0, 0);
    asm volatile("cp.async.commit_group;");
    if (nk > 1) { loadA(1, BKH); loadB(1, BKH); }
    asm volatile("cp.async.commit_group;");

    int buf = 0;
    for (int kb = 0; kb < nk; kb++) {
        asm volatile("cp.async.wait_group 1;");
        __syncthreads();
        if (kb + 2 < nk) {
            int s = (kb + 2) % NSTAGE;
            loadA(s, (kb + 2) * BKH);
            loadB(s, (kb + 2) * BKH);
        }
        asm volatile("cp.async.commit_group;");

        unsigned aStage = aBase + buf * (ASTAGE_H * 2);
        unsigned bStage = bBase + buf * (BSTAGE_H * 2);
        #pragma unroll
        for (int kk = 0; kk < BKH; kk += 16) {
            unsigned a_frag[2][4];
            #pragma unroll
            for (int mt = 0; mt < 2; mt++) {
                asm volatile("ldmatrix.sync.aligned.m8n8.x4.shared.b16 "
                             "{%0,%1,%2,%3}, [%4];"
                             : "=r"(a_frag[mt][0]), "=r"(a_frag[mt][1]),
                               "=r"(a_frag[mt][2]), "=r"(a_frag[mt][3])
                             : "r"(aStage + offA[mt] + kk * 2));
            }
            unsigned b_frag[NT][2];
            #pragma unroll
            for (int p = 0; p < NT / 2; p++) {
                asm volatile("ldmatrix.sync.aligned.m8n8.x4.shared.b16 "
                             "{%0,%1,%2,%3}, [%4];"
                             : "=r"(b_frag[2 * p][0]), "=r"(b_frag[2 * p][1]),
                               "=r"(b_frag[2 * p + 1][0]), "=r"(b_frag[2 * p + 1][1])
                             : "r"(bStage + offB[p] + kk * 2));
            }
            #pragma unroll
            for (int mt = 0; mt < 2; mt++)
                #pragma unroll
                for (int nt = 0; nt < NT; nt++) {
                    asm volatile(
                        "mma.sync.aligned.m16n8k16.row.col.f32.f16.f16.f32 "
                        "{%0,%1,%2,%3}, {%4,%5,%6,%7}, {%8,%9}, {%0,%1,%2,%3};"
                        : "+f"(acc[mt][nt][0]), "+f"(acc[mt][nt][1]),
                          "+f"(acc[mt][nt][2]), "+f"(acc[mt][nt][3])
                        : "r"(a_frag[mt][0]), "r"(a_frag[mt][1]),
                          "r"(a_frag[mt][2]), "r"(a_frag[mt][3]),
                          "r"(b_frag[nt][0]), "r"(b_frag[nt][1]));
                }
        }
        __syncthreads();
        buf = (buf + 1 == NSTAGE) ? 0 : buf + 1;
    }

    if (mode == 3) {
        if constexpr (NT == 8) {
            float* red = (float*)sm;
            #pragma unroll
            for (int mt = 0; mt < 2; mt++) {
                #pragma unroll
                for (int half = 0; half < 2; half++) {
                    int gr = rowBase + wm * 32 + mt * 16 + g + half * 8;
                    float ls = 0.f, lq = 0.f;
                    if (gr < M) {
                        #pragma unroll
                        for (int nt = 0; nt < NT; nt++) {
                            int gc = wn * 64 + nt * 8 + q * 2;
                            float* cp = (float*)Cv + (long)gr * N + gc;
                            float2 old = *(const float2*)cp;
                            float v0 = acc[mt][nt][half * 2 + 0] + bias[gc] + old.x;
                            float v1 = acc[mt][nt][half * 2 + 1] + bias[gc + 1] + old.y;
                            *(float2*)cp = make_float2(v0, v1);
                            acc[mt][nt][half * 2 + 0] = v0;
                            acc[mt][nt][half * 2 + 1] = v1;
                            ls += v0 + v1;
                            lq += v0 * v0 + v1 * v1;
                        }
                    }
                    ls += __shfl_xor_sync(0xffffffffu, ls, 1);
                    ls += __shfl_xor_sync(0xffffffffu, ls, 2);
                    lq += __shfl_xor_sync(0xffffffffu, lq, 1);
                    lq += __shfl_xor_sync(0xffffffffu, lq, 2);
                    if (q == 0 && gr < M) {
                        int idx = (((wm * 2 + mt) * 2 + half) * 8 + g) * 2 + wn;
                        red[idx] = ls;
                        red[512 + idx] = lq;
                    }
                }
            }
            __syncthreads();
            #pragma unroll
            for (int mt = 0; mt < 2; mt++) {
                #pragma unroll
                for (int half = 0; half < 2; half++) {
                    int gr = rowBase + wm * 32 + mt * 16 + g + half * 8;
                    if (gr >= M) continue;
                    int i0 = (((wm * 2 + mt) * 2 + half) * 8 + g) * 2;
                    float ts = red[i0] + red[i0 + 1];
                    float tq = red[512 + i0] + red[512 + i0 + 1];
                    float mu = ts * (1.0f / 128.0f);
                    float var = tq * (1.0f / 128.0f) - mu * mu;
                    float rsg = rsqrtf(var + 1e-5f);
                    #pragma unroll
                    for (int nt = 0; nt < NT; nt++) {
                        int gc = wn * 64 + nt * 8 + q * 2;
                        float v0 = (acc[mt][nt][half * 2 + 0] - mu) * rsg * lng[gc] + lnb[gc];
                        float v1 = (acc[mt][nt][half * 2 + 1] - mu) * rsg * lng[gc + 1] + lnb[gc + 1];
                        __half* xp = xnout + (long)gr * N + gc;
                        *(__half2*)xp = __floats2half2_rn(v0, v1);
                    }
                }
            }
        }
        return;
    }

    #pragma unroll
    for (int mt = 0; mt < 2; mt++) {
        #pragma unroll
        for (int half = 0; half < 2; half++) {
            int gr = rowBase + wm * 32 + mt * 16 + g + half * 8;
            if (gr >= M) continue;
            float dn = (mode == 0) ? degn[gr] : 0.0f;
            #pragma unroll
            for (int nt = 0; nt < NT; nt++) {
                int gc = colBase + wn * (NT * 8) + nt * 8 + q * 2;
                float v0 = acc[mt][nt][half * 2 + 0] + bias[gc];
                float v1 = acc[mt][nt][half * 2 + 1] + bias[gc + 1];
                if (mode == 1) {
                    float* cp = (float*)Cv + (long)gr * N + gc;
                    float2 old = *(const float2*)cp;
                    *(float2*)cp = make_float2(v0 + old.x, v1 + old.y);
                } else {
                    if (mode == 0) {
                        v0 += dn * wdegv[gc];
                        v1 += dn * wdegv[gc + 1];
                    } else {
                        v0 = 0.5f * v0 * (1.0f + erff(v0 * 0.70710678118654752f));
                        v1 = 0.5f * v1 * (1.0f + erff(v1 * 0.70710678118654752f));
                    }
                    __half* cp = (__half*)Cv + (long)gr * N + gc;
                    *(__half2*)cp = __floats2half2_rn(v0, v1);
                }
            }
        }
    }
}
#define SMEM8 (NSTAGE * (ASTAGE_H + 128 * LDH) * (int)sizeof(__half))
#define SMEM4 (NSTAGE * (ASTAGE_H + 64 * LDH) * (int)sizeof(__half))

// ---------------- fused single-pass CSR attention (warp per dst node) ----------
__device__ __forceinline__ float4 ld4h(const __half* p) {
    uint2 u = *(const uint2*)p;
    __half2 h0, h1;
    memcpy(&h0, &u.x, 4);
    memcpy(&h1, &u.y, 4);
    float2 a = __half22float2(h0);
    float2 b = __half22float2(h1);
    return make_float4(a.x, a.y, b.x, b.y);
}

__global__ __launch_bounds__(256) void k_attn(
    const int* __restrict__ off, const int* __restrict__ csr,
    const __half* __restrict__ qkv, __half* __restrict__ aggr,
    int nodeBase, int nodeEnd) {
    int w = nodeBase + ((blockIdx.x * blockDim.x + threadIdx.x) >> 5);
    int lane = threadIdx.x & 31;
    if (w >= nodeEnd) return;
    const int beg = off[w], end = off[w + 1];

    float4 qv = ld4h(qkv + (long)w * 384 + lane * 4);

    float s_acc = 0.0f;
    float ax = 0.f, ay = 0.f, az = 0.f, aw = 0.f;
    int e = beg;
    for (; e + 1 < end; e += 2) {
        int s0 = csr[e], s1 = csr[e + 1];
        float4 k0 = ld4h(qkv + (long)s0 * 384 + 128 + lane * 4);
        float4 k1 = ld4h(qkv + (long)s1 * 384 + 128 + lane * 4);
        float4 v0 = ld4h(qkv + (long)s0 * 384 + 256 + lane * 4);
        float4 v1 = ld4h(qkv + (long)s1 * 384 + 256 + lane * 4);
        float p0 = qv.x * k0.x + qv.y * k0.y + qv.z * k0.z + qv.w * k0.w;
        float p1 = qv.x * k1.x + qv.y * k1.y + qv.z * k1.z + qv.w * k1.w;
        p0 += __shfl_xor_sync(0xffffffffu, p0, 1);
        p0 += __shfl_xor_sync(0xffffffffu, p0, 2);
        p1 += __shfl_xor_sync(0xffffffffu, p1, 1);
        p1 += __shfl_xor_sync(0xffffffffu, p1, 2);
        float ex0 = __expf(fminf(fmaxf(p0 * 0.25f, -50.f), 50.f));
        float ex1 = __expf(fminf(fmaxf(p1 * 0.25f, -50.f), 50.f));
        s_acc += ex0 + ex1;
        ax += ex0 * v0.x + ex1 * v1.x;
        ay += ex0 * v0.y + ex1 * v1.y;
        az += ex0 * v0.z + ex1 * v1.z;
        aw += ex0 * v0.w + ex1 * v1.w;
    }
    if (e < end) {
        int s0 = csr[e];
        float4 k0 = ld4h(qkv + (long)s0 * 384 + 128 + lane * 4);
        float4 v0 = ld4h(qkv + (long)s0 * 384 + 256 + lane * 4);
        float p0 = qv.x * k0.x + qv.y * k0.y + qv.z * k0.z + qv.w * k0.w;
        p0 += __shfl_xor_sync(0xffffffffu, p0, 1);
        p0 += __shfl_xor_sync(0xffffffffu, p0, 2);
        float ex0 = __expf(fminf(fmaxf(p0 * 0.25f, -50.f), 50.f));
        s_acc += ex0;
        ax += ex0 * v0.x;
        ay += ex0 * v0.y;
        az += ex0 * v0.z;
        aw += ex0 * v0.w;
    }
    float rs = 1.0f / (s_acc + 1e-16f);
    __half2 h0 = __floats2half2_rn(ax * rs, ay * rs);
    __half2 h1 = __floats2half2_rn(az * rs, aw * rs);
    uint2 u = make_uint2(h2u(h0), h2u(h1));
    *(uint2*)(aggr + (long)w * DD + lane * 4) = u;
}

// ---------------- driver --------------------------------------------------------
extern "C" void kernel_launch(void* const* d_in, const int* in_sizes, int n_in,
                              void* d_out, int out_size) {
    const float* x    = (const float*)d_in[0];
    const int*   ei   = (const int*)d_in[1];
    const float* Wq   = (const float*)d_in[2];
    const float* Wk   = (const float*)d_in[3];
    const float* Wv   = (const float*)d_in[4];
    const float* Wo   = (const float*)d_in[5];
    const float* Wpos = (const float*)d_in[6];
    const float* Wdeg = (const float*)d_in[7];
    const float* W1   = (const float*)d_in[8];
    const float* W2   = (const float*)d_in[9];
    const float* bq   = (const float*)d_in[10];
    const float* bk   = (const float*)d_in[11];
    const float* bv   = (const float*)d_in[12];
    const float* bo   = (const float*)d_in[13];
    const float* bpos = (const float*)d_in[14];
    const float* bdeg = (const float*)d_in[15];
    const float* ln1b = (const float*)d_in[16];
    const float* ln2b = (const float*)d_in[17];
    const float* b1   = (const float*)d_in[18];
    const float* b2   = (const float*)d_in[19];
    const float* ln1g = (const float*)d_in[20];
    const float* ln2g = (const float*)d_in[21];
    float* xbuf = (float*)d_out;

    __half *xn, *qkv, *aggr, *hb, *weff, *wo, *w1, *w2;
    float *deg, *degn, *beff, *wde;
    int *ddeg, *off, *cur, *csr;
    double* stats;
    cudaGetSymbolAddress((void**)&xn,    g_xn);
    cudaGetSymbolAddress((void**)&qkv,   g_qkv);
    cudaGetSymbolAddress((void**)&aggr,  g_aggr);
    cudaGetSymbolAddress((void**)&hb,    g_h);
    cudaGetSymbolAddress((void**)&deg,   g_deg);
    cudaGetSymbolAddress((void**)&degn,  g_degn);
    cudaGetSymbolAddress((void**)&weff,  g_weff);
    cudaGetSymbolAddress((void**)&beff,  g_beff);
    cudaGetSymbolAddress((void**)&wde,   g_wdegeff);
    cudaGetSymbolAddress((void**)&wo,    g_wo);
    cudaGetSymbolAddress((void**)&w1,    g_w1);
    cudaGetSymbolAddress((void**)&w2,    g_w2);
    cudaGetSymbolAddress((void**)&ddeg,  g_ddeg);
    cudaGetSymbolAddress((void**)&off,   g_off);
    cudaGetSymbolAddress((void**)&cur,   g_cur);
    cudaGetSymbolAddress((void**)&csr,   g_csr);
    cudaGetSymbolAddress((void**)&stats, g_stats);

    cudaFuncSetAttribute((void*)gemm_hf<8>,
                         cudaFuncAttributeMaxDynamicSharedMemorySize, SMEM8);
    cudaFuncSetAttribute((void*)gemm_hf<4>,
                         cudaFuncAttributeMaxDynamicSharedMemorySize, SMEM4);

    static cudaStream_t s1 = nullptr, s2 = nullptr;
    static cudaEvent_t evRoot, evW, evC, evD, evCSR, evLN;
    static cudaEvent_t evM[LL], evS[LL], evSfin;
    if (!s1) {
        cudaStreamCreateWithFlags(&s1, cudaStreamNonBlocking);
        cudaStreamCreateWithFlags(&s2, cudaStreamNonBlocking);
        cudaEventCreateWithFlags(&evRoot, cudaEventDisableTiming);
        cudaEventCreateWithFlags(&evW,    cudaEventDisableTiming);
        cudaEventCreateWithFlags(&evC,    cudaEventDisableTiming);
        cudaEventCreateWithFlags(&evD,    cudaEventDisableTiming);
        cudaEventCreateWithFlags(&evCSR,  cudaEventDisableTiming);
        cudaEventCreateWithFlags(&evLN,   cudaEventDisableTiming);
        for (int l = 0; l < LL; l++) {
            cudaEventCreateWithFlags(&evM[l], cudaEventDisableTiming);
            cudaEventCreateWithFlags(&evS[l], cudaEventDisableTiming);
        }
        cudaEventCreateWithFlags(&evSfin, cudaEventDisableTiming);
    }

    const int lnBlocks = (NN + 7) / 8;

    // fork
    cudaEventRecord(evRoot, 0);
    cudaStreamWaitEvent(s1, evRoot, 0);
    cudaStreamWaitEvent(s2, evRoot, 0);

    // s2: degree stats + CSR build
    k_prep<<<(NN + 255) / 256, 256, 0, s2>>>(deg, ddeg, stats);
    k_degcount2<<<(EE + 255) / 256, 256, 0, s2>>>(ei, deg, ddeg);
    k_deg_reduce<<<148, 256, 0, s2>>>(deg, stats);
    k_deg_norm<<<(NN + 255) / 256, 256, 0, s2>>>(deg, stats, degn);
    cudaEventRecord(evD, s2);
    k_scan<<<1, 1024, 0, s2>>>(ddeg, off, cur, csr);
    k_csr_scatter<<<(EE + 255) / 256, 256, 0, s2>>>(ei, cur, csr);
    cudaEventRecord(evCSR, s2);

    // s1: weight preprocessing, then QKV half-1
    for (int l = 0; l < LL; l++) {
        k_weff<<<3 * DD, DD, 0, s1>>>(
            Wq + (size_t)l * DD * DD, Wk + (size_t)l * DD * DD,
            Wv + (size_t)l * DD * DD, Wpos + (size_t)l * DD * DD,
            Wdeg + (size_t)l * DD, bq + l * DD, bk + l * DD, bv + l * DD,
            bpos + l * DD, bdeg + l * DD,
            weff + (size_t)l * 3 * DD * DD, beff + l * 3 * DD, wde + l * 3 * DD);
    }
    cudaEventRecord(evW, s1);
    k_cvtw<<<dim3((DD * FFD + 255) / 256, LL), 256, 0, s1>>>(Wo, W1, W2, wo, w1, w2);
    cudaEventRecord(evC, s1);

    // main: x copy + LN1
    cudaMemcpyAsync(xbuf, x, (size_t)NN * DD * sizeof(float),
                    cudaMemcpyDeviceToDevice, 0);
    k_layernorm<<<lnBlocks, 256>>>(xbuf, ln1g, ln1b, xn);
    cudaEventRecord(evLN, 0);

    // initial QKV split across main (H0) / s1 (H1)
    cudaStreamWaitEvent(0, evW, 0);
    cudaStreamWaitEvent(0, evD, 0);
    gemm_hf<8><<<dim3(3, RB0), 256, SMEM8>>>(
        xn, weff, qkv, beff, wde, degn, nullptr, nullptr, nullptr,
        NN, 3 * DD, DD, 0, 0);
    cudaEventRecord(evM[0], 0);
    cudaStreamWaitEvent(s1, evLN, 0);
    cudaStreamWaitEvent(s1, evD, 0);
    gemm_hf<8><<<dim3(3, RB1), 256, SMEM8, s1>>>(
        xn, weff, qkv, beff, wde, degn, nullptr, nullptr, nullptr,
        NN, 3 * DD, DD, 0, RB0);
    cudaEventRecord(evS[0], s1);

    // CSR + cvtw joins
    cudaStreamWaitEvent(0, evCSR, 0);
    cudaStreamWaitEvent(0, evC, 0);
    cudaStreamWaitEvent(s1, evCSR, 0);

    for (int l = 0; l < LL; l++) {
        __half* wo_l = wo + (size_t)l * DD * DD;
        __half* w1_l = w1 + (size_t)l * FFD * DD;
        __half* w2_l = w2 + (size_t)l * DD * FFD;

        // cross-half joins: each half's attention needs BOTH QKV halves
        cudaStreamWaitEvent(0, evS[l], 0);
        cudaStreamWaitEvent(s1, evM[l], 0);

        // ---- H0 chain on main ----
        k_attn<<<NB0, 256>>>(off, csr, qkv, aggr, 0, SPLIT);
        gemm_hf<8><<<dim3(1, RB0), 256, SMEM8>>>(
            aggr, wo_l, xbuf, bo + l * DD, nullptr, nullptr,
            ln2g + l * DD, ln2b + l * DD, xn, NN, DD, DD, 3, 0);
        gemm_hf<8><<<dim3(4, RB0), 256, SMEM8>>>(
            xn, w1_l, hb, b1 + l * FFD, nullptr, nullptr, nullptr, nullptr, nullptr,
            NN, FFD, DD, 2, 0);

        // ---- H1 chain on s1 ----
        k_attn<<<NB1, 256, 0, s1>>>(off, csr, qkv, aggr, SPLIT, NN);
        gemm_hf<8><<<dim3(1, RB1), 256, SMEM8, s1>>>(
            aggr, wo_l, xbuf, bo + l * DD, nullptr, nullptr,
            ln2g + l * DD, ln2b + l * DD, xn, NN, DD, DD, 3, RB0);
        gemm_hf<8><<<dim3(4, RB1), 256, SMEM8, s1>>>(
            xn, w1_l, hb, b1 + l * FFD, nullptr, nullptr, nullptr, nullptr, nullptr,
            NN, FFD, DD, 2, RB0);

        if (l + 1 < LL) {
            int n = l + 1;
            gemm_hf<8><<<dim3(1, RB0), 256, SMEM8>>>(
                hb, w2_l, xbuf, b2 + l * DD, nullptr, nullptr,
                ln1g + n * DD, ln1b + n * DD, xn, NN, DD, FFD, 3, 0);
            gemm_hf<8><<<dim3(3, RB0), 256, SMEM8>>>(
                xn, weff + (size_t)n * 3 * DD * DD, qkv, beff + n * 3 * DD,
                wde + n * 3 * DD, degn, nullptr, nullptr, nullptr,
                NN, 3 * DD, DD, 0, 0);
            cudaEventRecord(evM[n], 0);

            gemm_hf<8><<<dim3(1, RB1), 256, SMEM8, s1>>>(
                hb, w2_l, xbuf, b2 + l * DD, nullptr, nullptr,
                ln1g + n * DD, ln1b + n * DD, xn, NN, DD, FFD, 3, RB0);
            gemm_hf<8><<<dim3(3, RB1), 256, SMEM8, s1>>>(
                xn, weff + (size_t)n * 3 * DD * DD, qkv, beff + n * 3 * DD,
                wde + n * 3 * DD, degn, nullptr, nullptr, nullptr,
                NN, 3 * DD, DD, 0, RB0);
            cudaEventRecord(evS[n], s1);
        } else {
            gemm_hf<4><<<dim3(2, RB0), 256, SMEM4>>>(
                hb, w2_l, xbuf, b2 + l * DD, nullptr, nullptr, nullptr, nullptr, nullptr,
                NN, DD, FFD, 1, 0);
            gemm_hf<4><<<dim3(2, RB1), 256, SMEM4, s1>>>(
                hb, w2_l, xbuf, b2 + l * DD, nullptr, nullptr, nullptr, nullptr, nullptr,
                NN, DD, FFD, 1, RB0);
            cudaEventRecord(evSfin, s1);
            cudaStreamWaitEvent(0, evSfin, 0);
        }
    }
}